// round 1
// baseline (speedup 1.0000x reference)
#include <cuda_runtime.h>
#include <cstdint>

// out[b, c, i] = in[b, c, parent_idx[i]]
// B=2, C=32, N_IN=1048576, N_OUT=2097152
// d_in[0] = input_features (float32, B*C*N_IN)
// d_in[1] = parent_idx     (int32,   N_OUT)
// d_out   = float32, B*C*N_OUT

#define N_IN_C   1048576
#define N_OUT_C  2097152
#define BC_C     64            // B*C
#define QUARTER  (N_OUT_C / 4) // 524288 float4 per plane

__global__ __launch_bounds__(256, 8)
void sample_particles_kernel(const float* __restrict__ in,
                             const int*   __restrict__ idx,
                             float*       __restrict__ out)
{
    const int bc  = blockIdx.y;                       // which (b,c) plane
    const int i4  = blockIdx.x * blockDim.x + threadIdx.x; // float4 slot in plane
    if (i4 >= QUARTER) return;

    const float* __restrict__ plane = in + (size_t)bc * N_IN_C;

    // 4 indices at once (idx array is L2-resident across all 64 planes)
    int4 p = __ldg(reinterpret_cast<const int4*>(idx) + i4);

    // 4 independent gathers — random within a 4 MiB, L2-resident plane
    float4 v;
    v.x = __ldg(plane + p.x);
    v.y = __ldg(plane + p.y);
    v.z = __ldg(plane + p.z);
    v.w = __ldg(plane + p.w);

    // streaming store: don't let the 512 MiB output evict gather planes from L2
    float4* dst = reinterpret_cast<float4*>(out) + (size_t)bc * QUARTER + i4;
    __stcs(dst, v);
}

extern "C" void kernel_launch(void* const* d_in, const int* in_sizes, int n_in,
                              void* d_out, int out_size)
{
    const float* in_feat = (const float*)d_in[0];
    const int*   parent  = (const int*)d_in[1];
    float*       out     = (float*)d_out;

    dim3 block(256);
    dim3 grid((QUARTER + 255) / 256, BC_C);  // 2048 x 64 blocks
    sample_particles_kernel<<<grid, block>>>(in_feat, parent, out);
}

// round 2
// speedup vs baseline: 3.7737x; 3.7737x over previous
#include <cuda_runtime.h>
#include <cstdint>

// out[b, c, i] = in[b, c, parent_idx[i]]
// B*C = 64, N_IN = 1048576, N_OUT = 2097152, fp32.
//
// Strategy: the same parent_idx is shared by all 64 (b,c) planes. Transpose
// input to tin[n][bc] so one gather index fetches a contiguous 256B row that
// serves all 64 planes (16 full LDG.128 instead of 64 scattered LDG.32).

#define N_IN_C   1048576
#define N_OUT_C  2097152
#define BC_C     64

// 256 MB scratch: transposed input, tin[n][bc]
__device__ __align__(256) float g_tin[(size_t)N_IN_C * BC_C];

// ---------------------------------------------------------------------------
// Kernel A: transpose in[64][1M] -> g_tin[1M][64]. Fully coalesced both ways.
// Block handles a 64(bc) x 64(n) tile. 256 threads.
// ---------------------------------------------------------------------------
__global__ __launch_bounds__(256)
void transpose_kernel(const float* __restrict__ in)
{
    __shared__ float t[64][65];            // [n-within-tile][bc], pad 65
    const int n0  = blockIdx.x * 64;
    const int tid = threadIdx.x;

    // Load: 64 bc-rows x 16 float4 (coalesced 256B per row)
#pragma unroll
    for (int it = 0; it < 4; ++it) {
        int fid = it * 256 + tid;
        int bc  = fid >> 4;                // 0..63
        int jc  = fid & 15;                // float4 slot within row
        float4 v = __ldg(reinterpret_cast<const float4*>(
                             in + (size_t)bc * N_IN_C + n0) + jc);
        t[jc * 4 + 0][bc] = v.x;
        t[jc * 4 + 1][bc] = v.y;
        t[jc * 4 + 2][bc] = v.z;
        t[jc * 4 + 3][bc] = v.w;
    }
    __syncthreads();

    // Write: 64 n-rows x 16 float4 over bc (coalesced 256B per row)
#pragma unroll
    for (int it = 0; it < 4; ++it) {
        int fid = it * 256 + tid;
        int j   = fid >> 4;                // n within tile
        int bq  = fid & 15;                // float4 slot over bc
        float4 v;
        v.x = t[j][bq * 4 + 0];
        v.y = t[j][bq * 4 + 1];
        v.z = t[j][bq * 4 + 2];
        v.w = t[j][bq * 4 + 3];
        *(reinterpret_cast<float4*>(g_tin + (size_t)(n0 + j) * BC_C) + bq) = v;
    }
}

// ---------------------------------------------------------------------------
// Kernel B: gather 64 output indices per block.
//   stage: smem[r][bc] = tin[idx[i0+r]][bc]   (contiguous 256B row per index)
//   write: out[bc][i0+r] coalesced (float4 over r), streaming stores.
// ---------------------------------------------------------------------------
__global__ __launch_bounds__(256)
void gather_kernel(const int* __restrict__ idx, float* __restrict__ out)
{
    __shared__ float t[64][65];            // [output-row r][bc], pad 65
    const int i0  = blockIdx.x * 64;
    const int tid = threadIdx.x;
    const int c   = tid & 15;              // float4 slot within 256B row
    const int r0  = tid >> 4;              // 0..15

    // Gather phase: 4 passes x 16 rows; each row = one 256B contiguous read
#pragma unroll
    for (int p = 0; p < 4; ++p) {
        int r  = p * 16 + r0;
        int pi = __ldg(idx + i0 + r);      // broadcast within 16-lane group
        float4 v = __ldg(reinterpret_cast<const float4*>(
                             g_tin + (size_t)pi * BC_C) + c);
        t[r][c * 4 + 0] = v.x;
        t[r][c * 4 + 1] = v.y;
        t[r][c * 4 + 2] = v.z;
        t[r][c * 4 + 3] = v.w;
    }
    __syncthreads();

    // Write phase: 4 passes x 16 bc; thread writes float4 of 4 consecutive r
#pragma unroll
    for (int p = 0; p < 4; ++p) {
        int bc = p * 16 + (tid >> 4);
        int rq = tid & 15;
        float4 v;
        v.x = t[rq * 4 + 0][bc];
        v.y = t[rq * 4 + 1][bc];
        v.z = t[rq * 4 + 2][bc];
        v.w = t[rq * 4 + 3][bc];
        // streaming store: keep the 512MB output from evicting g_tin in L2
        __stcs(reinterpret_cast<float4*>(out + (size_t)bc * N_OUT_C + i0) + rq, v);
    }
}

extern "C" void kernel_launch(void* const* d_in, const int* in_sizes, int n_in,
                              void* d_out, int out_size)
{
    const float* in_feat = (const float*)d_in[0];
    const int*   parent  = (const int*)d_in[1];
    float*       out     = (float*)d_out;

    transpose_kernel<<<N_IN_C / 64, 256>>>(in_feat);
    gather_kernel<<<N_OUT_C / 64, 256>>>(parent, out);
}